// round 12
// baseline (speedup 1.0000x reference)
#include <cuda_runtime.h>
#include <cstddef>

#define B_ROWS   262144
#define TILE     128
#define NTHREADS 512

typedef unsigned long long ull;

// packed fp32x2 FMA: d = a*b + d (elementwise on 2 packed floats)
__device__ __forceinline__ void ffma2(ull& d, ull a, ull b) {
    asm("fma.rn.f32x2 %0, %1, %2, %0;" : "+l"(d) : "l"(a), "l"(b));
}
__device__ __forceinline__ ull pack2(float lo, float hi) {
    ull r;
    asm("mov.b64 %0, {%1, %2};" : "=l"(r) : "r"(__float_as_uint(lo)), "r"(__float_as_uint(hi)));
    return r;
}
__device__ __forceinline__ void unpack2(ull v, float& lo, float& hi) {
    unsigned int l, h;
    asm("mov.b64 {%0, %1}, %2;" : "=r"(l), "=r"(h) : "l"(v));
    lo = __uint_as_float(l); hi = __uint_as_float(h);
}

// shared-memory layout (floats).
// R1/R2: 16384-float regions. Phase1: R1={W0,xmT}, R2=z1/h1T. Phase2: R1=W1, R3=z2/h2T.
// Phase3: R1,R2 double-buffer the staged Wp group (h1 dead after residual); R3=h2T.
#define R1      0
#define XMOFF   4096
#define R2      16384
#define R3      32768
#define VEC     49152            // b0,g0,be0,b1,g1,be1 : 6*128 = 768
#define BPOFF   (VEC + 768)      // bp repacked stride 28: 32*28 = 896
#define MUOFF   (BPOFF + 896)    // 128
#define RSOFF   (MUOFF + 128)    // 128
#define REDOFF  (RSOFF + 128)    // 1024 (sum/sumsq partials, ld reduce)
#define SMEM_FLOATS (REDOFF + 1024)   // 52096 floats = 208384 B

__global__ void __launch_bounds__(NTHREADS, 1)
spline_coupling_kernel(const float* __restrict__ x,
                       const float* __restrict__ W0, const float* __restrict__ b0,
                       const float* __restrict__ g0, const float* __restrict__ be0,
                       const float* __restrict__ W1, const float* __restrict__ b1,
                       const float* __restrict__ g1, const float* __restrict__ be1,
                       const float* __restrict__ Wp, const float* __restrict__ bp,
                       float* __restrict__ out)
{
    extern __shared__ float sm[];
    const int tid  = threadIdx.x;
    const int w    = tid >> 5;
    const int lane = tid & 31;
    const int row0 = blockIdx.x * TILE;

    // ---------------- Phase 0: load W0, vectors, bp, x tile ----------------
    for (int i = tid; i < 32 * 128; i += NTHREADS) sm[R1 + i] = W0[i];

    if (tid < 128)      sm[VEC +   0 + tid]        = b0[tid];
    else if (tid < 256) sm[VEC + 128 + (tid-128)]  = g0[tid-128];
    else if (tid < 384) sm[VEC + 256 + (tid-256)]  = be0[tid-256];
    else                sm[VEC + 384 + (tid-384)]  = b1[tid-384];
    if (tid < 128)      sm[VEC + 512 + tid]        = g1[tid];
    else if (tid < 256) sm[VEC + 640 + (tid-128)]  = be1[tid-128];

    // bp repacked: dim-major stride 28 (25 used) so per-dim pairs are 16B-aligned
    for (int i = tid; i < 800; i += NTHREADS) {
        int d = i / 25, j = i - d * 25;
        sm[BPOFF + d * 28 + j] = bp[i];
    }

    // x tile: read float2 (xm,xu) coalesced; stash xm transposed; copy xm -> y even lanes
    // (streaming store: out is write-once, never re-read by this kernel)
    for (int i = tid; i < TILE * 32; i += NTHREADS) {
        int row = i >> 5, k = i & 31;
        float2 v = reinterpret_cast<const float2*>(x)[(size_t)(row0 + row) * 32 + k];
        sm[R1 + XMOFF + k * 129 + row] = v.x;
        __stcs(&out[(size_t)(row0 + row) * 64 + 2 * k], v.x);
    }
    __syncthreads();

    // ---------------- Phase 1: z1 = xm @ W0 + b0 -> R2 (transposed) ----------------
    for (int task = w; task < 128; task += 16) {
        int rg = task & 3;
        int c0 = (task >> 2) << 2;
        int r  = (rg << 5) | lane;
        float a0 = sm[VEC + c0], a1 = sm[VEC + c0 + 1];
        float a2 = sm[VEC + c0 + 2], a3 = sm[VEC + c0 + 3];
        #pragma unroll
        for (int k = 0; k < 32; k++) {
            float xv = sm[R1 + XMOFF + k * 129 + r];
            float4 wv = *reinterpret_cast<const float4*>(&sm[R1 + k * 128 + c0]);
            a0 = fmaf(xv, wv.x, a0); a1 = fmaf(xv, wv.y, a1);
            a2 = fmaf(xv, wv.z, a2); a3 = fmaf(xv, wv.w, a3);
        }
        sm[R2 + (c0+0)*128 + r] = a0;
        sm[R2 + (c0+1)*128 + r] = a1;
        sm[R2 + (c0+2)*128 + r] = a2;
        sm[R2 + (c0+3)*128 + r] = a3;
    }
    __syncthreads();

    // LN1 stats
    {
        int q = tid >> 7, r = tid & 127;
        float s = 0.f, ss = 0.f;
        #pragma unroll
        for (int c = 0; c < 32; c++) {
            float v = sm[R2 + (q * 32 + c) * 128 + r];
            s += v; ss = fmaf(v, v, ss);
        }
        sm[REDOFF + (q << 7) + r]       = s;
        sm[REDOFF + 512 + (q << 7) + r] = ss;
    }
    __syncthreads();
    if (tid < 128) {
        float s  = sm[REDOFF+tid] + sm[REDOFF+128+tid] + sm[REDOFF+256+tid] + sm[REDOFF+384+tid];
        float ss = sm[REDOFF+512+tid] + sm[REDOFF+640+tid] + sm[REDOFF+768+tid] + sm[REDOFF+896+tid];
        float mu  = s * (1.f / 128.f);
        float var = ss * (1.f / 128.f) - mu * mu;
        sm[MUOFF + tid] = mu;
        sm[RSOFF + tid] = rsqrtf(var + 1e-6f);
    }
    __syncthreads();
    // apply LN1 + relu (R2 in place), and load W1 into R1 (W0/xm dead)
    for (int i = tid; i < 16384; i += NTHREADS) {
        int c = i >> 7, r = i & 127;
        float v = sm[R2 + i];
        v = (v - sm[MUOFF + r]) * sm[RSOFF + r] * sm[VEC + 128 + c] + sm[VEC + 256 + c];
        sm[R2 + i] = fmaxf(v, 0.f);
    }
    for (int i = tid; i < 16384; i += NTHREADS) sm[R1 + i] = W1[i];
    __syncthreads();

    // ---------------- Phase 2: z2 = h1 @ W1 + b1 -> R3 (packed f32x2, 8 cols/task) ----------------
    for (int task = w; task < 64; task += 16) {
        int rg = task & 3;
        int c0 = (task >> 2) << 3;
        int r  = (rg << 5) | lane;
        ulonglong2 bq0 = *reinterpret_cast<const ulonglong2*>(&sm[VEC + 384 + c0]);
        ulonglong2 bq1 = *reinterpret_cast<const ulonglong2*>(&sm[VEC + 384 + c0 + 4]);
        ull acc0 = bq0.x, acc1 = bq0.y, acc2 = bq1.x, acc3 = bq1.y;
        #pragma unroll 8
        for (int k = 0; k < 128; k++) {
            float hv = sm[R2 + k * 128 + r];
            ull h2 = pack2(hv, hv);
            ulonglong2 wp0 = *reinterpret_cast<const ulonglong2*>(&sm[R1 + k * 128 + c0]);
            ulonglong2 wp1 = *reinterpret_cast<const ulonglong2*>(&sm[R1 + k * 128 + c0 + 4]);
            ffma2(acc0, h2, wp0.x);
            ffma2(acc1, h2, wp0.y);
            ffma2(acc2, h2, wp1.x);
            ffma2(acc3, h2, wp1.y);
        }
        float o0, o1, o2, o3, o4, o5, o6, o7;
        unpack2(acc0, o0, o1); unpack2(acc1, o2, o3);
        unpack2(acc2, o4, o5); unpack2(acc3, o6, o7);
        sm[R3 + (c0+0)*128 + r] = o0;
        sm[R3 + (c0+1)*128 + r] = o1;
        sm[R3 + (c0+2)*128 + r] = o2;
        sm[R3 + (c0+3)*128 + r] = o3;
        sm[R3 + (c0+4)*128 + r] = o4;
        sm[R3 + (c0+5)*128 + r] = o5;
        sm[R3 + (c0+6)*128 + r] = o6;
        sm[R3 + (c0+7)*128 + r] = o7;
    }
    __syncthreads();

    // ---- early-issue Phase-3 loads: group-0 Wp stage + this thread's 8 xu values ----
    // (R1 is dead from here on; LDG latency hides behind LN2 stats + residual below)
    const int dl = tid >> 7;     // 0..3  local dim within group (whole warp shares one dim)
    const int r3 = tid & 127;    // row   (lanes = consecutive rows)
    float wreg0[25];
    #pragma unroll
    for (int s = 0; s < 25; s++) {
        int i = tid + s * NTHREADS;
        int k = i / 100;
        int j = i - k * 100;
        wreg0[s] = Wp[(size_t)k * 800 + j];
    }
    float xuv[8];
    #pragma unroll
    for (int g = 0; g < 8; g++)
        xuv[g] = __ldg(&x[(size_t)(row0 + r3) * 64 + 2 * (g * 4 + dl) + 1]);

    // LN2 stats
    {
        int q = tid >> 7, r = tid & 127;
        float s = 0.f, ss = 0.f;
        #pragma unroll
        for (int c = 0; c < 32; c++) {
            float v = sm[R3 + (q * 32 + c) * 128 + r];
            s += v; ss = fmaf(v, v, ss);
        }
        sm[REDOFF + (q << 7) + r]       = s;
        sm[REDOFF + 512 + (q << 7) + r] = ss;
    }
    __syncthreads();
    if (tid < 128) {
        float s  = sm[REDOFF+tid] + sm[REDOFF+128+tid] + sm[REDOFF+256+tid] + sm[REDOFF+384+tid];
        float ss = sm[REDOFF+512+tid] + sm[REDOFF+640+tid] + sm[REDOFF+768+tid] + sm[REDOFF+896+tid];
        float mu  = s * (1.f / 128.f);
        float var = ss * (1.f / 128.f) - mu * mu;
        sm[MUOFF + tid] = mu;
        sm[RSOFF + tid] = rsqrtf(var + 1e-6f);
    }
    __syncthreads();
    // apply LN2 + relu + residual (h2 = relu(LN(z2)) + h1) -> R3,
    // and store prefetched Wp group 0 into R1 (no reader of R1 since Phase-2 sync)
    for (int i = tid; i < 16384; i += NTHREADS) {
        int c = i >> 7, r = i & 127;
        float v = sm[R3 + i];
        v = (v - sm[MUOFF + r]) * sm[RSOFF + r] * sm[VEC + 512 + c] + sm[VEC + 640 + c];
        sm[R3 + i] = fmaxf(v, 0.f) + sm[R2 + i];
    }
    #pragma unroll
    for (int s = 0; s < 25; s++) {
        int i  = tid + s * NTHREADS;
        int k  = i / 100;
        int j  = i - k * 100;
        int d2 = j / 25;
        int jj = j - d2 * 25;
        sm[R1 + k * 112 + d2 * 28 + jj] = wreg0[s];
    }
    __syncthreads();

    // ---------------- Phase 3: GEMM3 (double-buffered Wp, packed f32x2) + spline ----------------
    const int r = r3;
    float ldacc = 0.f;

    for (int g = 0; g < 8; g++) {
        const float* buf  = sm + ((g & 1) ? R2 : R1);
        float*       nbuf = sm + ((g & 1) ? R1 : R2);

        // issue next group's 25 LDGs early; latency hides behind the FMA block below
        float wreg[25];
        if (g < 7) {
            #pragma unroll
            for (int s = 0; s < 25; s++) {
                int i = tid + s * NTHREADS;
                int k = i / 100;
                int j = i - k * 100;
                wreg[s] = Wp[(size_t)k * 800 + (g + 1) * 100 + j];
            }
        }

        const int dim = g * 4 + dl;
        // accumulators: 12 packed pairs + 1 scalar, init from repacked bias
        ull accp[12];
        {
            const ulonglong2* bq = reinterpret_cast<const ulonglong2*>(&sm[BPOFF + dim * 28]);
            #pragma unroll
            for (int j = 0; j < 6; j++) { ulonglong2 q = bq[j]; accp[2*j] = q.x; accp[2*j+1] = q.y; }
        }
        float acc24 = sm[BPOFF + dim * 28 + 24];

        const float* wpB = buf + dl * 28;
        #pragma unroll 2
        for (int k = 0; k < 128; k++) {
            float a = sm[R3 + k * 128 + r];
            ull a2 = pack2(a, a);
            const ulonglong2* w2 = reinterpret_cast<const ulonglong2*>(wpB + k * 112);
            #pragma unroll
            for (int jv = 0; jv < 6; jv++) {
                ulonglong2 p = w2[jv];
                ffma2(accp[2*jv],   a2, p.x);
                ffma2(accp[2*jv+1], a2, p.y);
            }
            acc24 = fmaf(a, wpB[k * 112 + 24], acc24);
        }

        // store next group's stage while the spline epilogue (register-only) runs
        if (g < 7) {
            #pragma unroll
            for (int s = 0; s < 25; s++) {
                int i  = tid + s * NTHREADS;
                int k  = i / 100;
                int j  = i - k * 100;
                int d2 = j / 25;
                int jj = j - d2 * 25;
                nbuf[k * 112 + d2 * 28 + jj] = wreg[s];
            }
        }

        // unpack accumulators
        float acc[25];
        #pragma unroll
        for (int j = 0; j < 12; j++) unpack2(accp[j], acc[2*j], acc[2*j+1]);
        acc[24] = acc24;

        // ---- spline epilogue for (row r, dim) ----
        // widths softmax + cumsum (needed in full for the bin search)
        float mw = acc[0];
        #pragma unroll
        for (int j = 1; j < 8; j++) mw = fmaxf(mw, acc[j]);
        float ew[8], swsum = 0.f;
        #pragma unroll
        for (int j = 0; j < 8; j++) { ew[j] = __expf(acc[j] - mw); swsum += ew[j]; }
        float invw = __fdividef(1.f, swsum);
        float wv[8], cw[9];
        cw[0] = -3.f;
        #pragma unroll
        for (int j = 0; j < 8; j++) {
            wv[j] = (0.001f + 0.992f * ew[j] * invw) * 6.0f;
            cw[j+1] = cw[j] + wv[j];
        }

        float xu = xuv[g];
        bool inside = (xu > -3.f) && (xu < 3.f);
        float xc = fminf(fmaxf(xu, -3.f), 3.f);

        int idx = 0;
        #pragma unroll
        for (int j = 1; j < 8; j++) if (xc >= cw[j]) idx = j;

        // heights softmax + cumsum (full set needed for sum and y_k)
        float mh = acc[8];
        #pragma unroll
        for (int j = 1; j < 8; j++) mh = fmaxf(mh, acc[8 + j]);
        float eh[8], shsum = 0.f;
        #pragma unroll
        for (int j = 0; j < 8; j++) { eh[j] = __expf(acc[8 + j] - mh); shsum += eh[j]; }
        float invh = __fdividef(1.f, shsum);
        float hv[8], ch[9];
        ch[0] = -3.f;
        #pragma unroll
        for (int j = 0; j < 8; j++) {
            hv[j] = (0.001f + 0.992f * eh[j] * invh) * 6.0f;
            ch[j+1] = ch[j] + hv[j];
        }

        // select bin-local params; softplus only on the two derivative logits used
        float w_k = wv[0], x_k = cw[0], h_k = hv[0], y_k = ch[0];
        float z_k = acc[16], z_k1 = acc[17];
        #pragma unroll
        for (int j = 1; j < 8; j++)
            if (idx == j) {
                w_k = wv[j]; x_k = cw[j]; h_k = hv[j]; y_k = ch[j];
                z_k = acc[16 + j]; z_k1 = acc[17 + j];
            }
        float d_k  = fmaxf(z_k,  0.f) + __logf(1.f + __expf(-fabsf(z_k)))  + 0.001f;
        float d_k1 = fmaxf(z_k1, 0.f) + __logf(1.f + __expf(-fabsf(z_k1))) + 0.001f;

        float s_  = __fdividef(h_k, w_k);
        float th  = __fdividef(xc - x_k, w_k);
        float om  = 1.f - th;
        float t1m = th * om;
        float den = fmaf(d_k1 + d_k - 2.f * s_, t1m, s_);
        float y_in = y_k + __fdividef(h_k * fmaf(s_ * th, th, d_k * t1m), den);
        float ldn  = fmaf(d_k1 * th, th, fmaf(2.f * s_, t1m, d_k * om * om));
        // ld = log(s^2 * ldn / den^2): one log instead of three (all args > 0)
        float ld_in = __logf(__fdividef(s_ * s_ * ldn, den * den));

        __stcs(&out[(size_t)(row0 + r) * 64 + 2 * dim + 1], inside ? y_in : xu);
        ldacc += inside ? ld_in : 0.f;

        __syncthreads();   // buffer handoff: reads of buf done, writes to nbuf visible
    }

    // log_det: sum the 4 partial sums per row (each thread held 8 dims of its row)
    sm[REDOFF + dl * 128 + r] = ldacc;
    __syncthreads();
    if (tid < 128) {
        float v = sm[REDOFF + tid] + sm[REDOFF + 128 + tid]
                + sm[REDOFF + 256 + tid] + sm[REDOFF + 384 + tid];
        __stcs(&out[(size_t)B_ROWS * 64 + row0 + tid], v);
    }
}

extern "C" void kernel_launch(void* const* d_in, const int* in_sizes, int n_in,
                              void* d_out, int out_size)
{
    const float* x   = (const float*)d_in[0];
    const float* W0  = (const float*)d_in[1];
    const float* b0  = (const float*)d_in[2];
    const float* g0  = (const float*)d_in[3];
    const float* be0 = (const float*)d_in[4];
    const float* W1  = (const float*)d_in[5];
    const float* b1  = (const float*)d_in[6];
    const float* g1  = (const float*)d_in[7];
    const float* be1 = (const float*)d_in[8];
    const float* Wp  = (const float*)d_in[9];
    const float* bp  = (const float*)d_in[10];

    const int smem_bytes = SMEM_FLOATS * 4;
    cudaFuncSetAttribute(spline_coupling_kernel,
                         cudaFuncAttributeMaxDynamicSharedMemorySize, smem_bytes);
    spline_coupling_kernel<<<B_ROWS / TILE, NTHREADS, smem_bytes>>>(
        x, W0, b0, g0, be0, W1, b1, g1, be1, Wp, bp, (float*)d_out);
}

// round 15
// speedup vs baseline: 1.0647x; 1.0647x over previous
#include <cuda_runtime.h>
#include <cstddef>

#define B_ROWS   262144
#define TILE     128
#define NTHREADS 256

typedef unsigned long long ull;

// packed fp32x2 FMA: d = a*b + d (elementwise on 2 packed floats)
__device__ __forceinline__ void ffma2(ull& d, ull a, ull b) {
    asm("fma.rn.f32x2 %0, %1, %2, %0;" : "+l"(d) : "l"(a), "l"(b));
}
__device__ __forceinline__ ull pack2(float lo, float hi) {
    ull r;
    asm("mov.b64 %0, {%1, %2};" : "=l"(r) : "r"(__float_as_uint(lo)), "r"(__float_as_uint(hi)));
    return r;
}
__device__ __forceinline__ void unpack2(ull v, float& lo, float& hi) {
    unsigned int l, h;
    asm("mov.b64 {%0, %1}, %2;" : "=r"(l), "=r"(h) : "l"(v));
    lo = __uint_as_float(l); hi = __uint_as_float(h);
}

// shared-memory layout (float indices).
// Phases 1-2: R1={W0,xmT}/W1, R2=h1T, R3=h2T.
// Phase 3: STG (R1∪R2 region) = staged Wp pass (8 dims × stride 28 = 224 floats/k × 128 k).
#define R1      0
#define XMOFF   4096
#define R2      16384
#define R3      32768
#define STG     0
#define SSTRIDE 224
#define VEC     49152            // b0,g0,be0,b1,g1,be1 : 6*128 = 768
#define BPOFF   (VEC + 768)      // bp repacked stride 28: 32*28 = 896
#define MUOFF   (BPOFF + 896)    // 128
#define RSOFF   (MUOFF + 128)    // 128
#define REDOFF  (RSOFF + 128)    // 1024 (sum/sumsq partials, ld reduce)
#define SMEM_FLOATS (REDOFF + 1024)   // 52096 floats = 208384 B

__global__ void __launch_bounds__(NTHREADS, 1)
spline_coupling_kernel(const float* __restrict__ x,
                       const float* __restrict__ W0, const float* __restrict__ b0,
                       const float* __restrict__ g0, const float* __restrict__ be0,
                       const float* __restrict__ W1, const float* __restrict__ b1,
                       const float* __restrict__ g1, const float* __restrict__ be1,
                       const float* __restrict__ Wp, const float* __restrict__ bp,
                       float* __restrict__ out)
{
    extern __shared__ float sm[];
    const int tid  = threadIdx.x;
    const int w    = tid >> 5;
    const int lane = tid & 31;
    const int row0 = blockIdx.x * TILE;

    // ---------------- Phase 0: load W0, vectors, bp, x tile ----------------
    for (int i = tid; i < 32 * 128; i += NTHREADS) sm[R1 + i] = W0[i];

    for (int i = tid; i < 768; i += NTHREADS) {
        int a = i >> 7, o = i & 127;
        float v;
        if      (a == 0) v = b0[o];
        else if (a == 1) v = g0[o];
        else if (a == 2) v = be0[o];
        else if (a == 3) v = b1[o];
        else if (a == 4) v = g1[o];
        else             v = be1[o];
        sm[VEC + i] = v;
    }

    // bp repacked: dim-major stride 28 (25 used) so per-dim pairs are 16B-aligned
    for (int i = tid; i < 800; i += NTHREADS) {
        int d = i / 25, j = i - d * 25;
        sm[BPOFF + d * 28 + j] = bp[i];
    }

    // x tile: read float2 (xm,xu) coalesced; stash xm transposed; copy xm -> y even lanes
    for (int i = tid; i < TILE * 32; i += NTHREADS) {
        int row = i >> 5, k = i & 31;
        float2 v = reinterpret_cast<const float2*>(x)[(size_t)(row0 + row) * 32 + k];
        sm[R1 + XMOFF + k * 129 + row] = v.x;
        __stcs(&out[(size_t)(row0 + row) * 64 + 2 * k], v.x);
    }
    __syncthreads();

    // ---------------- Phase 1: z1 = xm @ W0 + b0 -> R2 (transposed) ----------------
    for (int task = w; task < 128; task += 8) {
        int rg = task & 3;
        int c0 = (task >> 2) << 2;
        int r  = (rg << 5) | lane;
        float a0 = sm[VEC + c0], a1 = sm[VEC + c0 + 1];
        float a2 = sm[VEC + c0 + 2], a3 = sm[VEC + c0 + 3];
        #pragma unroll
        for (int k = 0; k < 32; k++) {
            float xv = sm[R1 + XMOFF + k * 129 + r];
            float4 wv = *reinterpret_cast<const float4*>(&sm[R1 + k * 128 + c0]);
            a0 = fmaf(xv, wv.x, a0); a1 = fmaf(xv, wv.y, a1);
            a2 = fmaf(xv, wv.z, a2); a3 = fmaf(xv, wv.w, a3);
        }
        sm[R2 + (c0+0)*128 + r] = a0;
        sm[R2 + (c0+1)*128 + r] = a1;
        sm[R2 + (c0+2)*128 + r] = a2;
        sm[R2 + (c0+3)*128 + r] = a3;
    }
    __syncthreads();

    // LN1 stats (256 threads: q in {0,1}, 64 cols each)
    {
        int q = tid >> 7, r = tid & 127;
        float s = 0.f, ss = 0.f;
        #pragma unroll
        for (int c = 0; c < 64; c++) {
            float v = sm[R2 + (q * 64 + c) * 128 + r];
            s += v; ss = fmaf(v, v, ss);
        }
        sm[REDOFF + (q << 7) + r]       = s;
        sm[REDOFF + 512 + (q << 7) + r] = ss;
    }
    __syncthreads();
    if (tid < 128) {
        float s  = sm[REDOFF + tid] + sm[REDOFF + 128 + tid];
        float ss = sm[REDOFF + 512 + tid] + sm[REDOFF + 640 + tid];
        float mu  = s * (1.f / 128.f);
        float var = ss * (1.f / 128.f) - mu * mu;
        sm[MUOFF + tid] = mu;
        sm[RSOFF + tid] = rsqrtf(var + 1e-6f);
    }
    __syncthreads();
    // apply LN1 + relu (R2 in place), and load W1 into R1 (W0/xm dead)
    for (int i = tid; i < 16384; i += NTHREADS) {
        int c = i >> 7, r = i & 127;
        float v = sm[R2 + i];
        v = (v - sm[MUOFF + r]) * sm[RSOFF + r] * sm[VEC + 128 + c] + sm[VEC + 256 + c];
        sm[R2 + i] = fmaxf(v, 0.f);
    }
    for (int i = tid; i < 16384; i += NTHREADS) sm[R1 + i] = W1[i];
    __syncthreads();

    // ---------------- Phase 2: z2 = h1 @ W1 + b1 -> R3 (packed f32x2, 8 cols/task) ----------------
    for (int task = w; task < 64; task += 8) {
        int rg = task & 3;
        int c0 = (task >> 2) << 3;
        int r  = (rg << 5) | lane;
        ulonglong2 bq0 = *reinterpret_cast<const ulonglong2*>(&sm[VEC + 384 + c0]);
        ulonglong2 bq1 = *reinterpret_cast<const ulonglong2*>(&sm[VEC + 384 + c0 + 4]);
        ull acc0 = bq0.x, acc1 = bq0.y, acc2 = bq1.x, acc3 = bq1.y;
        #pragma unroll 8
        for (int k = 0; k < 128; k++) {
            float hv = sm[R2 + k * 128 + r];
            ull h2 = pack2(hv, hv);
            ulonglong2 wp0 = *reinterpret_cast<const ulonglong2*>(&sm[R1 + k * 128 + c0]);
            ulonglong2 wp1 = *reinterpret_cast<const ulonglong2*>(&sm[R1 + k * 128 + c0 + 4]);
            ffma2(acc0, h2, wp0.x);
            ffma2(acc1, h2, wp0.y);
            ffma2(acc2, h2, wp1.x);
            ffma2(acc3, h2, wp1.y);
        }
        float o0, o1, o2, o3, o4, o5, o6, o7;
        unpack2(acc0, o0, o1); unpack2(acc1, o2, o3);
        unpack2(acc2, o4, o5); unpack2(acc3, o6, o7);
        sm[R3 + (c0+0)*128 + r] = o0;
        sm[R3 + (c0+1)*128 + r] = o1;
        sm[R3 + (c0+2)*128 + r] = o2;
        sm[R3 + (c0+3)*128 + r] = o3;
        sm[R3 + (c0+4)*128 + r] = o4;
        sm[R3 + (c0+5)*128 + r] = o5;
        sm[R3 + (c0+6)*128 + r] = o6;
        sm[R3 + (c0+7)*128 + r] = o7;
    }
    __syncthreads();

    // LN2 stats
    {
        int q = tid >> 7, r = tid & 127;
        float s = 0.f, ss = 0.f;
        #pragma unroll
        for (int c = 0; c < 64; c++) {
            float v = sm[R3 + (q * 64 + c) * 128 + r];
            s += v; ss = fmaf(v, v, ss);
        }
        sm[REDOFF + (q << 7) + r]       = s;
        sm[REDOFF + 512 + (q << 7) + r] = ss;
    }
    __syncthreads();
    if (tid < 128) {
        float s  = sm[REDOFF + tid] + sm[REDOFF + 128 + tid];
        float ss = sm[REDOFF + 512 + tid] + sm[REDOFF + 640 + tid];
        float mu  = s * (1.f / 128.f);
        float var = ss * (1.f / 128.f) - mu * mu;
        sm[MUOFF + tid] = mu;
        sm[RSOFF + tid] = rsqrtf(var + 1e-6f);
    }
    __syncthreads();
    // apply LN2 + relu + residual (h2 = relu(LN(z2)) + h1) -> R3
    for (int i = tid; i < 16384; i += NTHREADS) {
        int c = i >> 7, r = i & 127;
        float v = sm[R3 + i];
        v = (v - sm[MUOFF + r]) * sm[RSOFF + r] * sm[VEC + 512 + c] + sm[VEC + 640 + c];
        sm[R3 + i] = fmaxf(v, 0.f) + sm[R2 + i];
    }
    __syncthreads();   // R2/R1 now dead -> reusable as STG

    // ---------------- Phase 3: GEMM3 + spline. 8 warps; warp = 1 dim x 128 rows;
    // thread = 4 consecutive rows (LDS.128). 4 passes of 8 dims. ----------------
    const int wq    = w;            // warp id 0..7
    const int rbase = lane << 2;    // rows rbase..rbase+3
    float ldacc[4] = {0.f, 0.f, 0.f, 0.f};

    for (int p = 0; p < 4; p++) {
        // stage 8 dims of Wp: sm[STG + k*224 + wd*28 + jj] = Wp[k][ (p*8+wd)*25 + jj ]
        for (int i = tid; i < 128 * 200; i += NTHREADS) {
            int k  = i / 200;
            int j  = i - k * 200;
            int wd = j / 25;
            int jj = j - wd * 25;
            sm[STG + k * SSTRIDE + wd * 28 + jj] = Wp[(size_t)k * 800 + (p * 8 + wd) * 25 + jj];
        }
        __syncthreads();

        const int dim = p * 8 + wq;

        // xu for this thread's 4 rows (latency hides under the k-loop)
        float xuv[4];
        #pragma unroll
        for (int rr = 0; rr < 4; rr++)
            xuv[rr] = __ldg(&x[(size_t)(row0 + rbase + rr) * 64 + 2 * dim + 1]);

        // accumulators: 4 rows x (12 packed pairs + 1 scalar)
        ull ap[48]; float a24[4];
        {
            const ulonglong2* bq = reinterpret_cast<const ulonglong2*>(&sm[BPOFF + dim * 28]);
            #pragma unroll
            for (int jv = 0; jv < 6; jv++) {
                ulonglong2 q = bq[jv];
                ap[     2*jv] = q.x; ap[     2*jv+1] = q.y;
                ap[12 + 2*jv] = q.x; ap[12 + 2*jv+1] = q.y;
                ap[24 + 2*jv] = q.x; ap[24 + 2*jv+1] = q.y;
                ap[36 + 2*jv] = q.x; ap[36 + 2*jv+1] = q.y;
            }
            float b24 = sm[BPOFF + dim * 28 + 24];
            a24[0] = b24; a24[1] = b24; a24[2] = b24; a24[3] = b24;
        }

        const float* wpB = sm + STG + wq * 28;
        #pragma unroll 2
        for (int k = 0; k < 128; k++) {
            float4 av = *reinterpret_cast<const float4*>(&sm[R3 + k * 128 + rbase]);
            ull q0 = pack2(av.x, av.x), q1 = pack2(av.y, av.y);
            ull q2 = pack2(av.z, av.z), q3 = pack2(av.w, av.w);
            const ulonglong2* w2 = reinterpret_cast<const ulonglong2*>(wpB + k * SSTRIDE);
            #pragma unroll
            for (int jv = 0; jv < 6; jv++) {
                ulonglong2 pz = w2[jv];
                ffma2(ap[     2*jv], q0, pz.x); ffma2(ap[     2*jv+1], q0, pz.y);
                ffma2(ap[12 + 2*jv], q1, pz.x); ffma2(ap[12 + 2*jv+1], q1, pz.y);
                ffma2(ap[24 + 2*jv], q2, pz.x); ffma2(ap[24 + 2*jv+1], q2, pz.y);
                ffma2(ap[36 + 2*jv], q3, pz.x); ffma2(ap[36 + 2*jv+1], q3, pz.y);
            }
            float w24 = wpB[k * SSTRIDE + 24];
            a24[0] = fmaf(av.x, w24, a24[0]);
            a24[1] = fmaf(av.y, w24, a24[1]);
            a24[2] = fmaf(av.z, w24, a24[2]);
            a24[3] = fmaf(av.w, w24, a24[3]);
        }

        // ---- spline epilogue: 4 rows, same dim ----
        #pragma unroll
        for (int rr = 0; rr < 4; rr++) {
            float acc[25];
            #pragma unroll
            for (int j = 0; j < 12; j++) unpack2(ap[rr * 12 + j], acc[2*j], acc[2*j+1]);
            acc[24] = a24[rr];

            // widths softmax + cumsum
            float mw = acc[0];
            #pragma unroll
            for (int j = 1; j < 8; j++) mw = fmaxf(mw, acc[j]);
            float ew[8], swsum = 0.f;
            #pragma unroll
            for (int j = 0; j < 8; j++) { ew[j] = __expf(acc[j] - mw); swsum += ew[j]; }
            float invw = __fdividef(1.f, swsum);
            float wv[8], cw[9];
            cw[0] = -3.f;
            #pragma unroll
            for (int j = 0; j < 8; j++) {
                wv[j] = (0.001f + 0.992f * ew[j] * invw) * 6.0f;
                cw[j+1] = cw[j] + wv[j];
            }

            float xu = xuv[rr];
            bool inside = (xu > -3.f) && (xu < 3.f);
            float xc = fminf(fmaxf(xu, -3.f), 3.f);

            int idx = 0;
            #pragma unroll
            for (int j = 1; j < 8; j++) if (xc >= cw[j]) idx = j;

            // heights softmax + cumsum
            float mh = acc[8];
            #pragma unroll
            for (int j = 1; j < 8; j++) mh = fmaxf(mh, acc[8 + j]);
            float eh[8], shsum = 0.f;
            #pragma unroll
            for (int j = 0; j < 8; j++) { eh[j] = __expf(acc[8 + j] - mh); shsum += eh[j]; }
            float invh = __fdividef(1.f, shsum);
            float hv[8], ch[9];
            ch[0] = -3.f;
            #pragma unroll
            for (int j = 0; j < 8; j++) {
                hv[j] = (0.001f + 0.992f * eh[j] * invh) * 6.0f;
                ch[j+1] = ch[j] + hv[j];
            }

            // select bin-local params; softplus only on the two logits used
            float w_k = wv[0], x_k = cw[0], h_k = hv[0], y_k = ch[0];
            float z_k = acc[16], z_k1 = acc[17];
            #pragma unroll
            for (int j = 1; j < 8; j++)
                if (idx == j) {
                    w_k = wv[j]; x_k = cw[j]; h_k = hv[j]; y_k = ch[j];
                    z_k = acc[16 + j]; z_k1 = acc[17 + j];
                }
            float d_k  = fmaxf(z_k,  0.f) + __logf(1.f + __expf(-fabsf(z_k)))  + 0.001f;
            float d_k1 = fmaxf(z_k1, 0.f) + __logf(1.f + __expf(-fabsf(z_k1))) + 0.001f;

            float s_  = __fdividef(h_k, w_k);
            float th  = __fdividef(xc - x_k, w_k);
            float om  = 1.f - th;
            float t1m = th * om;
            float den = fmaf(d_k1 + d_k - 2.f * s_, t1m, s_);
            float y_in = y_k + __fdividef(h_k * fmaf(s_ * th, th, d_k * t1m), den);
            float ldn  = fmaf(d_k1 * th, th, fmaf(2.f * s_, t1m, d_k * om * om));
            float ld_in = __logf(__fdividef(s_ * s_ * ldn, den * den));

            __stcs(&out[(size_t)(row0 + rbase + rr) * 64 + 2 * dim + 1], inside ? y_in : xu);
            ldacc[rr] += inside ? ld_in : 0.f;
        }

        __syncthreads();   // all reads of STG done before next pass overwrites
    }

    // log_det: per-warp per-row partials (each warp summed 4 dims for every row)
    #pragma unroll
    for (int rr = 0; rr < 4; rr++)
        sm[REDOFF + wq * 128 + rbase + rr] = ldacc[rr];
    __syncthreads();
    if (tid < 128) {
        float v = 0.f;
        #pragma unroll
        for (int ww = 0; ww < 8; ww++) v += sm[REDOFF + ww * 128 + tid];
        __stcs(&out[(size_t)B_ROWS * 64 + row0 + tid], v);
    }
}

extern "C" void kernel_launch(void* const* d_in, const int* in_sizes, int n_in,
                              void* d_out, int out_size)
{
    const float* x   = (const float*)d_in[0];
    const float* W0  = (const float*)d_in[1];
    const float* b0  = (const float*)d_in[2];
    const float* g0  = (const float*)d_in[3];
    const float* be0 = (const float*)d_in[4];
    const float* W1  = (const float*)d_in[5];
    const float* b1  = (const float*)d_in[6];
    const float* g1  = (const float*)d_in[7];
    const float* be1 = (const float*)d_in[8];
    const float* Wp  = (const float*)d_in[9];
    const float* bp  = (const float*)d_in[10];

    const int smem_bytes = SMEM_FLOATS * 4;
    cudaFuncSetAttribute(spline_coupling_kernel,
                         cudaFuncAttributeMaxDynamicSharedMemorySize, smem_bytes);
    spline_coupling_kernel<<<B_ROWS / TILE, NTHREADS, smem_bytes>>>(
        x, W0, b0, g0, be0, W1, b1, g1, be1, Wp, bp, (float*)d_out);
}